// round 9
// baseline (speedup 1.0000x reference)
#include <cuda_runtime.h>
#include <cuda_bf16.h>
#include <cstdint>

#define NN 20000
#define EE 320000
#define CC 128
#define BB 20
#define RCUT 5.0f
#define EPSN 1e-8f
#define PI_F 3.14159265358979323846f

typedef unsigned long long u64;

// ---------------- scratch (static device globals; no allocation) -------------
__device__ float g_x[NN * 384];     // x = silu(q@W1+b1)@W2+b2, [N,384]
__device__ float g_dq[NN * 128];    // scatter accum dq
__device__ float g_dmu[NN * 384];   // scatter accum dmu [N,3,128]

__device__ __forceinline__ float silu_f(float v) {
    return v / (1.0f + __expf(-v));
}

// ---- packed fp32x2 helpers (Blackwell FFMA2 via PTX) ----
__device__ __forceinline__ u64 pack2(float lo, float hi) {
    u64 r; asm("mov.b64 %0, {%1, %2};" : "=l"(r) : "f"(lo), "f"(hi)); return r;
}
__device__ __forceinline__ void unpack2(u64 p, float& lo, float& hi) {
    asm("mov.b64 {%0, %1}, %2;" : "=f"(lo), "=f"(hi) : "l"(p));
}
__device__ __forceinline__ u64 ffma2(u64 a, u64 b, u64 c) {
    u64 d; asm("fma.rn.f32x2 %0, %1, %2, %3;" : "=l"(d) : "l"(a), "l"(b), "l"(c));
    return d;
}

__device__ __forceinline__ void red_add_f(float* p, float v) {
    asm volatile("red.global.add.f32 [%0], %1;" :: "l"(p), "f"(v) : "memory");
}

// ============================================================================
// K1: per-node context MLP  x = silu(q@W1+b1)@W2+b2   (+ zero dq/dmu accums)
// 256 threads = 2 groups x 128 channels; 16 nodes/block (8 per group).
// grid = N/16 = 1250
// ============================================================================
__global__ __launch_bounds__(256) void k_node_mlp(
    const float* __restrict__ q,
    const float* __restrict__ W1, const float* __restrict__ b1,
    const float* __restrict__ W2, const float* __restrict__ b2)
{
    __shared__ float sT[128 * 16];   // transposed activations [k][n(16)]
    const int t  = threadIdx.x;
    const int tc = t & 127;          // channel
    const int g  = t >> 7;           // node-group 0/1
    const int n0 = blockIdx.x * 16;
    const int ng = n0 + g * 8;

    // zero the scatter accumulators for this node range (before K2 runs)
    for (int idx = t; idx < 16 * 128; idx += 256) {
        g_dq[n0 * 128 + idx] = 0.0f;
    }
    for (int idx = t; idx < 16 * 384; idx += 256) {
        g_dmu[n0 * 384 + idx] = 0.0f;
    }

    // stage qT: sT[k=tc][node]
#pragma unroll
    for (int n = 0; n < 8; n++) sT[tc * 16 + g * 8 + n] = q[(ng + n) * 128 + tc];
    __syncthreads();

    // h[n][tc] = silu(b1[tc] + sum_k q[n][k] * W1[k][tc])   (8 nodes of my group)
    u64 acc[4];
    {
        const float bb = __ldg(&b1[tc]);
        const u64 bb2 = pack2(bb, bb);
#pragma unroll
        for (int u = 0; u < 4; u++) acc[u] = bb2;
    }
#pragma unroll 4
    for (int k = 0; k < 128; k++) {
        const float w = __ldg(&W1[k * 128 + tc]);
        const u64 w2 = pack2(w, w);
        const ulonglong2* r = (const ulonglong2*)&sT[k * 16 + g * 8];
        const ulonglong2 a0 = r[0], a1 = r[1];
        acc[0] = ffma2(a0.x, w2, acc[0]); acc[1] = ffma2(a0.y, w2, acc[1]);
        acc[2] = ffma2(a1.x, w2, acc[2]); acc[3] = ffma2(a1.y, w2, acc[3]);
    }
    __syncthreads();
#pragma unroll
    for (int u = 0; u < 4; u++) {
        float lo, hi; unpack2(acc[u], lo, hi);
        sT[tc * 16 + g * 8 + 2 * u]     = silu_f(lo);
        sT[tc * 16 + g * 8 + 2 * u + 1] = silu_f(hi);
    }
    __syncthreads();

    // x[n][m] for m in {tc, tc+128, tc+256}
    u64 y0[4], y1[4], y2[4];
    {
        const float c0 = __ldg(&b2[tc]);
        const float c1 = __ldg(&b2[128 + tc]);
        const float c2 = __ldg(&b2[256 + tc]);
        const u64 p0 = pack2(c0, c0), p1 = pack2(c1, c1), p2 = pack2(c2, c2);
#pragma unroll
        for (int u = 0; u < 4; u++) { y0[u] = p0; y1[u] = p1; y2[u] = p2; }
    }
#pragma unroll 4
    for (int k = 0; k < 128; k++) {
        const float f0 = __ldg(&W2[k * 384 + tc]);
        const float f1 = __ldg(&W2[k * 384 + 128 + tc]);
        const float f2 = __ldg(&W2[k * 384 + 256 + tc]);
        const u64 w0 = pack2(f0, f0), w1 = pack2(f1, f1), w2 = pack2(f2, f2);
        const ulonglong2* r = (const ulonglong2*)&sT[k * 16 + g * 8];
        const ulonglong2 h0 = r[0], h1 = r[1];
        y0[0] = ffma2(h0.x, w0, y0[0]); y0[1] = ffma2(h0.y, w0, y0[1]);
        y0[2] = ffma2(h1.x, w0, y0[2]); y0[3] = ffma2(h1.y, w0, y0[3]);
        y1[0] = ffma2(h0.x, w1, y1[0]); y1[1] = ffma2(h0.y, w1, y1[1]);
        y1[2] = ffma2(h1.x, w1, y1[2]); y1[3] = ffma2(h1.y, w1, y1[3]);
        y2[0] = ffma2(h0.x, w2, y2[0]); y2[1] = ffma2(h0.y, w2, y2[1]);
        y2[2] = ffma2(h1.x, w2, y2[2]); y2[3] = ffma2(h1.y, w2, y2[3]);
    }
#pragma unroll
    for (int u = 0; u < 4; u++) {
        float a, b;
        unpack2(y0[u], a, b);
        g_x[(ng + 2 * u) * 384 + tc] = a;       g_x[(ng + 2 * u + 1) * 384 + tc] = b;
        unpack2(y1[u], a, b);
        g_x[(ng + 2 * u) * 384 + 128 + tc] = a; g_x[(ng + 2 * u + 1) * 384 + 128 + tc] = b;
        unpack2(y2[u], a, b);
        g_x[(ng + 2 * u) * 384 + 256 + tc] = a; g_x[(ng + 2 * u + 1) * 384 + 256 + tc] = b;
    }
}

// ============================================================================
// K2: edge messages, channel-owning threads. 128 threads; thread t owns
// channels {t, 128+t, 256+t}. Filter weights live in registers (pre-packed for
// ffma2); attrs staged packed in smem and read via broadcast LDS.64.
// TE=64 edges per block; grid = E/TE = 5000.
// ============================================================================
#define TE 64
__global__ __launch_bounds__(128) void k_edge(
    const int*   __restrict__ eidx,     // [2,E]
    const float* __restrict__ ew,       // [E]
    const float* __restrict__ evers,    // [E,3]
    const float* __restrict__ eattr,    // [E,B]
    const float* __restrict__ Wf,       // [B,384]
    const float* __restrict__ bf,       // [384]
    const float* __restrict__ mu)       // [N,3,128]
{
    __shared__ u64   sA2[BB * TE];      // pack2(a,a) at [b*TE + e]  (10 KB)
    __shared__ float sFc[TE];
    __shared__ float sV[3 * TE];
    __shared__ int   sIJ[2 * TE];

    const int t = threadIdx.x;
    const int e0 = blockIdx.x * TE;

    // stage edge data (before weight preload so LDGs overlap)
    for (int idx = t; idx < TE * BB; idx += 128) {
        const int e = idx / BB, b = idx % BB;
        const float a = __ldg(&eattr[(e0 + e) * BB + b]);
        sA2[b * TE + e] = pack2(a, a);
    }
    if (t < TE) {
        const int e = e0 + t;
        sIJ[t]      = eidx[e];
        sIJ[TE + t] = eidx[EE + e];
        const float wgt = __ldg(&ew[e]);
        sFc[t] = (wgt < RCUT) ? 0.5f * (cosf((PI_F / RCUT) * wgt) + 1.0f) : 0.0f;
        sV[t]          = __ldg(&evers[e * 3 + 0]);
        sV[TE + t]     = __ldg(&evers[e * 3 + 1]);
        sV[2 * TE + t] = __ldg(&evers[e * 3 + 2]);
    }

    // register-resident filter weights for my 3 channels
    u64 wAB[BB], wCC[BB];
#pragma unroll
    for (int b = 0; b < BB; b++) {
        const float wa = __ldg(&Wf[b * 384 + t]);
        const float wb = __ldg(&Wf[b * 384 + 128 + t]);
        const float wc = __ldg(&Wf[b * 384 + 256 + t]);
        wAB[b] = pack2(wa, wb);
        wCC[b] = pack2(wc, wc);
    }
    const u64 bAB = pack2(__ldg(&bf[t]), __ldg(&bf[128 + t]));
    const u64 bCC = pack2(__ldg(&bf[256 + t]), 0.0f);
    __syncthreads();

    for (int e = 0; e < TE; e++) {
        const int i = sIJ[e];
        const int j = sIJ[TE + e];
        const float fc = sFc[e];
        const float vx = sV[e], vy = sV[TE + e], vz = sV[2 * TE + e];

        u64 acc = bAB, accC = bCC;
#pragma unroll
        for (int b = 0; b < BB; b++) {
            const u64 a2 = sA2[b * TE + e];   // broadcast LDS.64
            acc  = ffma2(wAB[b], a2, acc);
            accC = ffma2(wCC[b], a2, accC);
        }
        float wijA, wijB, wijC, dead;
        unpack2(acc, wijA, wijB);
        unpack2(accC, wijC, dead);
        wijA *= fc; wijB *= fc; wijC *= fc;

        const float xA = __ldg(&g_x[j * 384 + t]);
        const float xB = __ldg(&g_x[j * 384 + 128 + t]);
        const float xC = __ldg(&g_x[j * 384 + 256 + t]);
        const float m0 = __ldg(&mu[j * 384 + t]);
        const float m1 = __ldg(&mu[j * 384 + 128 + t]);
        const float m2 = __ldg(&mu[j * 384 + 256 + t]);

        const float dq = xA * wijA;
        const float dR = xB * wijB;
        const float dM = xC * wijC;

        red_add_f(&g_dq[i * 128 + t], dq);
        red_add_f(&g_dmu[i * 384 + t],       dR * vx + dM * m0);
        red_add_f(&g_dmu[i * 384 + 128 + t], dR * vy + dM * m1);
        red_add_f(&g_dmu[i * 384 + 256 + t], dR * vz + dM * m2);
    }
}

// ============================================================================
// K3: PaiNN mixing. block = 128 threads, 8 nodes per block, grid = 2500.
// ============================================================================
__global__ __launch_bounds__(128) void k_mix(
    const float* __restrict__ q,
    const float* __restrict__ mu,
    const float* __restrict__ Wmix,   // [128,256]
    const float* __restrict__ Wm1,    // [256,128]
    const float* __restrict__ bm1,    // [128]
    const float* __restrict__ Wm2,    // [128,384]
    const float* __restrict__ bm2,    // [384]
    float* __restrict__ out_q,        // [N,128]
    float* __restrict__ out_mu)       // [N,3,128]
{
    __shared__ float sMuT[128 * 24];   // [k][v*8+n]  (mun transposed)
    __shared__ float sAW[128 * 24];    // stash of mu_W per (t-channel)[v*8+n]
    __shared__ float sCtx[256 * 8];    // [k][n]
    __shared__ float sH2[128 * 8];     // [k][n]
    const int t = threadIdx.x;
    const int n0 = blockIdx.x * 8;

    float qn[8];
#pragma unroll
    for (int v = 0; v < 3; v++)
#pragma unroll
        for (int n = 0; n < 8; n++) {
            const int gi = (n0 + n) * 384 + v * 128 + t;
            sMuT[t * 24 + v * 8 + n] = mu[gi] + g_dmu[gi];
        }
#pragma unroll
    for (int n = 0; n < 8; n++)
        qn[n] = q[(n0 + n) * 128 + t] + g_dq[(n0 + n) * 128 + t];
    __syncthreads();

    // fused: mu_V and mu_W GEMMs over one sMuT pass
    u64 aV[12], aW[12];
#pragma unroll
    for (int u = 0; u < 12; u++) { aV[u] = 0ull; aW[u] = 0ull; }
#pragma unroll 2
    for (int k = 0; k < 128; k++) {
        const float wv = __ldg(&Wmix[k * 256 + t]);
        const float ww = __ldg(&Wmix[k * 256 + 128 + t]);
        const u64 wv2 = pack2(wv, wv);
        const u64 ww2 = pack2(ww, ww);
        const ulonglong2* r = (const ulonglong2*)&sMuT[k * 24];
#pragma unroll
        for (int u = 0; u < 6; u++) {
            const ulonglong2 m = r[u];
            aV[2 * u]     = ffma2(m.x, wv2, aV[2 * u]);
            aV[2 * u + 1] = ffma2(m.y, wv2, aV[2 * u + 1]);
            aW[2 * u]     = ffma2(m.x, ww2, aW[2 * u]);
            aW[2 * u + 1] = ffma2(m.y, ww2, aW[2 * u + 1]);
        }
    }
    float av[24], aw[24];
#pragma unroll
    for (int u = 0; u < 12; u++) {
        unpack2(aV[u], av[2 * u], av[2 * u + 1]);
        unpack2(aW[u], aw[2 * u], aw[2 * u + 1]);
    }

    float Vn[8], sdot[8];
#pragma unroll
    for (int n = 0; n < 8; n++) {
        Vn[n] = sqrtf(av[n] * av[n] + av[8 + n] * av[8 + n]
                      + av[16 + n] * av[16 + n] + EPSN);
        sdot[n] = av[n] * aw[n] + av[8 + n] * aw[8 + n] + av[16 + n] * aw[16 + n];
    }
#pragma unroll
    for (int u = 0; u < 24; u++) sAW[t * 24 + u] = aw[u];

#pragma unroll
    for (int n = 0; n < 8; n++) {
        sCtx[t * 8 + n] = qn[n];
        sCtx[(128 + t) * 8 + n] = Vn[n];
    }
    __syncthreads();

    u64 h[4];
    {
        const float bb = __ldg(&bm1[t]);
        const u64 bb2 = pack2(bb, bb);
#pragma unroll
        for (int u = 0; u < 4; u++) h[u] = bb2;
    }
#pragma unroll 4
    for (int k = 0; k < 256; k++) {
        const float w = __ldg(&Wm1[k * 128 + t]);
        const u64 w2 = pack2(w, w);
        const ulonglong2* r = (const ulonglong2*)&sCtx[k * 8];
        const ulonglong2 ca = r[0], cb = r[1];
        h[0] = ffma2(ca.x, w2, h[0]); h[1] = ffma2(ca.y, w2, h[1]);
        h[2] = ffma2(cb.x, w2, h[2]); h[3] = ffma2(cb.y, w2, h[3]);
    }
#pragma unroll
    for (int u = 0; u < 4; u++) {
        float lo, hi; unpack2(h[u], lo, hi);
        sH2[t * 8 + 2 * u]     = silu_f(lo);
        sH2[t * 8 + 2 * u + 1] = silu_f(hi);
    }
    __syncthreads();

    u64 ya[4], yb[4], yc[4];
    {
        const float c0 = __ldg(&bm2[t]);
        const float c1 = __ldg(&bm2[128 + t]);
        const float c2 = __ldg(&bm2[256 + t]);
        const u64 pa = pack2(c0, c0), pb = pack2(c1, c1), pc = pack2(c2, c2);
#pragma unroll
        for (int u = 0; u < 4; u++) { ya[u] = pa; yb[u] = pb; yc[u] = pc; }
    }
#pragma unroll 2
    for (int k = 0; k < 128; k++) {
        const float f0 = __ldg(&Wm2[k * 384 + t]);
        const float f1 = __ldg(&Wm2[k * 384 + 128 + t]);
        const float f2 = __ldg(&Wm2[k * 384 + 256 + t]);
        const u64 w0 = pack2(f0, f0), w1 = pack2(f1, f1), w2 = pack2(f2, f2);
        const ulonglong2* r = (const ulonglong2*)&sH2[k * 8];
        const ulonglong2 ha = r[0], hb = r[1];
        ya[0] = ffma2(ha.x, w0, ya[0]); ya[1] = ffma2(ha.y, w0, ya[1]);
        ya[2] = ffma2(hb.x, w0, ya[2]); ya[3] = ffma2(hb.y, w0, ya[3]);
        yb[0] = ffma2(ha.x, w1, yb[0]); yb[1] = ffma2(ha.y, w1, yb[1]);
        yb[2] = ffma2(hb.x, w1, yb[2]); yb[3] = ffma2(hb.y, w1, yb[3]);
        yc[0] = ffma2(ha.x, w2, yc[0]); yc[1] = ffma2(ha.y, w2, yc[1]);
        yc[2] = ffma2(hb.x, w2, yc[2]); yc[3] = ffma2(hb.y, w2, yc[3]);
    }
    float Ya[8], Yb[8], Yc[8];
#pragma unroll
    for (int u = 0; u < 4; u++) {
        unpack2(ya[u], Ya[2 * u], Ya[2 * u + 1]);
        unpack2(yb[u], Yb[2 * u], Yb[2 * u + 1]);
        unpack2(yc[u], Yc[2 * u], Yc[2 * u + 1]);
    }

#pragma unroll
    for (int n = 0; n < 8; n++) {
        out_q[(n0 + n) * 128 + t] = qn[n] + Ya[n] + Yc[n] * sdot[n];
#pragma unroll
        for (int v = 0; v < 3; v++)
            out_mu[(n0 + n) * 384 + v * 128 + t] =
                sMuT[t * 24 + v * 8 + n] + Yb[n] * sAW[t * 24 + v * 8 + n];
    }
}

// ============================================================================
extern "C" void kernel_launch(void* const* d_in, const int* in_sizes, int n_in,
                              void* d_out, int out_size)
{
    const float* q     = (const float*)d_in[0];
    const float* mu    = (const float*)d_in[1];
    const int*   eidx  = (const int*)d_in[2];
    const float* ew    = (const float*)d_in[3];
    const float* evers = (const float*)d_in[4];
    const float* eattr = (const float*)d_in[5];
    const float* Wf    = (const float*)d_in[6];
    const float* bf    = (const float*)d_in[7];
    const float* W1    = (const float*)d_in[8];
    const float* b1    = (const float*)d_in[9];
    const float* W2    = (const float*)d_in[10];
    const float* b2    = (const float*)d_in[11];
    const float* Wmix  = (const float*)d_in[12];
    const float* Wm1   = (const float*)d_in[13];
    const float* bm1   = (const float*)d_in[14];
    const float* Wm2   = (const float*)d_in[15];
    const float* bm2   = (const float*)d_in[16];

    float* out   = (float*)d_out;
    float* out_q = out;
    float* out_mu = out + (size_t)NN * 128;

    k_node_mlp<<<NN / 16, 256>>>(q, W1, b1, W2, b2);
    k_edge<<<EE / TE, 128>>>(eidx, ew, evers, eattr, Wf, bf, mu);
    k_mix<<<NN / 8, 128>>>(q, mu, Wmix, Wm1, bm1, Wm2, bm2, out_q, out_mu);
}

// round 11
// speedup vs baseline: 1.2405x; 1.2405x over previous
#include <cuda_runtime.h>
#include <cuda_bf16.h>
#include <cstdint>

#define NN 20000
#define EE 320000
#define CC 128
#define BB 20
#define RCUT 5.0f
#define EPSN 1e-8f
#define PI_F 3.14159265358979323846f

typedef unsigned long long u64;

// ---------------- scratch (static device globals; no allocation) -------------
__device__ float g_x[NN * 384];     // x = silu(q@W1+b1)@W2+b2, [N,384]
__device__ float g_dq[NN * 128];    // scatter accum dq
__device__ float g_dmu[NN * 384];   // scatter accum dmu [N,3,128]

__device__ __forceinline__ float silu_f(float v) {
    return v / (1.0f + __expf(-v));
}

// ---- packed fp32x2 helpers (Blackwell FFMA2 via PTX) ----
__device__ __forceinline__ u64 pack2(float lo, float hi) {
    u64 r; asm("mov.b64 %0, {%1, %2};" : "=l"(r) : "f"(lo), "f"(hi)); return r;
}
__device__ __forceinline__ void unpack2(u64 p, float& lo, float& hi) {
    asm("mov.b64 {%0, %1}, %2;" : "=f"(lo), "=f"(hi) : "l"(p));
}
__device__ __forceinline__ u64 ffma2(u64 a, u64 b, u64 c) {
    u64 d; asm("fma.rn.f32x2 %0, %1, %2, %3;" : "=l"(d) : "l"(a), "l"(b), "l"(c));
    return d;
}

__device__ __forceinline__ void red_add_v4(float* ptr, float4 v) {
    asm volatile("red.global.add.v4.f32 [%0], {%1, %2, %3, %4};"
                 :: "l"(ptr), "f"(v.x), "f"(v.y), "f"(v.z), "f"(v.w)
                 : "memory");
}

// ============================================================================
// K1: per-node context MLP  (verbatim R5 version — measured 89us)
// block = 128 threads, 16 nodes per block, grid = N/16 = 1250
// ============================================================================
__global__ __launch_bounds__(128) void k_node_mlp(
    const float* __restrict__ q,
    const float* __restrict__ W1, const float* __restrict__ b1,
    const float* __restrict__ W2, const float* __restrict__ b2)
{
    __shared__ float sT[128 * 16];   // transposed activations [k][n]
    const int t = threadIdx.x;
    const int n0 = blockIdx.x * 16;

    // zero the scatter accumulators for this node range (before K2 runs)
#pragma unroll
    for (int n = 0; n < 16; n++) {
        g_dq[(n0 + n) * 128 + t] = 0.0f;
        g_dmu[(n0 + n) * 384 + t] = 0.0f;
        g_dmu[(n0 + n) * 384 + 128 + t] = 0.0f;
        g_dmu[(n0 + n) * 384 + 256 + t] = 0.0f;
    }

    // stage qT: sT[k=t][n]
#pragma unroll
    for (int n = 0; n < 16; n++) sT[t * 16 + n] = q[(n0 + n) * 128 + t];
    __syncthreads();

    // h[n][t] = silu(b1[t] + sum_k q[n][k] * W1[k][t])
    u64 acc[8];
    {
        const float bb = __ldg(&b1[t]);
        const u64 bb2 = pack2(bb, bb);
#pragma unroll
        for (int u = 0; u < 8; u++) acc[u] = bb2;
    }
#pragma unroll 4
    for (int k = 0; k < 128; k++) {
        const float w = __ldg(&W1[k * 128 + t]);
        const u64 w2 = pack2(w, w);
        const ulonglong2* r = (const ulonglong2*)&sT[k * 16];
        const ulonglong2 a0 = r[0], a1 = r[1], a2 = r[2], a3 = r[3];
        acc[0] = ffma2(a0.x, w2, acc[0]); acc[1] = ffma2(a0.y, w2, acc[1]);
        acc[2] = ffma2(a1.x, w2, acc[2]); acc[3] = ffma2(a1.y, w2, acc[3]);
        acc[4] = ffma2(a2.x, w2, acc[4]); acc[5] = ffma2(a2.y, w2, acc[5]);
        acc[6] = ffma2(a3.x, w2, acc[6]); acc[7] = ffma2(a3.y, w2, acc[7]);
    }
    __syncthreads();
#pragma unroll
    for (int u = 0; u < 8; u++) {
        float lo, hi; unpack2(acc[u], lo, hi);
        sT[t * 16 + 2 * u]     = silu_f(lo);
        sT[t * 16 + 2 * u + 1] = silu_f(hi);
    }
    __syncthreads();

    // x[n][m] for m in {t, t+128, t+256}
    u64 y0[8], y1[8], y2[8];
    {
        const float c0 = __ldg(&b2[t]);
        const float c1 = __ldg(&b2[128 + t]);
        const float c2 = __ldg(&b2[256 + t]);
        const u64 p0 = pack2(c0, c0), p1 = pack2(c1, c1), p2 = pack2(c2, c2);
#pragma unroll
        for (int u = 0; u < 8; u++) { y0[u] = p0; y1[u] = p1; y2[u] = p2; }
    }
#pragma unroll 2
    for (int k = 0; k < 128; k++) {
        const u64 w0 = pack2(__ldg(&W2[k * 384 + t]),       __ldg(&W2[k * 384 + t]));
        const u64 w1 = pack2(__ldg(&W2[k * 384 + 128 + t]), __ldg(&W2[k * 384 + 128 + t]));
        const u64 w2 = pack2(__ldg(&W2[k * 384 + 256 + t]), __ldg(&W2[k * 384 + 256 + t]));
        const ulonglong2* r = (const ulonglong2*)&sT[k * 16];
        const ulonglong2 h0 = r[0], h1 = r[1], h2 = r[2], h3 = r[3];
        y0[0] = ffma2(h0.x, w0, y0[0]); y0[1] = ffma2(h0.y, w0, y0[1]);
        y0[2] = ffma2(h1.x, w0, y0[2]); y0[3] = ffma2(h1.y, w0, y0[3]);
        y0[4] = ffma2(h2.x, w0, y0[4]); y0[5] = ffma2(h2.y, w0, y0[5]);
        y0[6] = ffma2(h3.x, w0, y0[6]); y0[7] = ffma2(h3.y, w0, y0[7]);
        y1[0] = ffma2(h0.x, w1, y1[0]); y1[1] = ffma2(h0.y, w1, y1[1]);
        y1[2] = ffma2(h1.x, w1, y1[2]); y1[3] = ffma2(h1.y, w1, y1[3]);
        y1[4] = ffma2(h2.x, w1, y1[4]); y1[5] = ffma2(h2.y, w1, y1[5]);
        y1[6] = ffma2(h3.x, w1, y1[6]); y1[7] = ffma2(h3.y, w1, y1[7]);
        y2[0] = ffma2(h0.x, w2, y2[0]); y2[1] = ffma2(h0.y, w2, y2[1]);
        y2[2] = ffma2(h1.x, w2, y2[2]); y2[3] = ffma2(h1.y, w2, y2[3]);
        y2[4] = ffma2(h2.x, w2, y2[4]); y2[5] = ffma2(h2.y, w2, y2[5]);
        y2[6] = ffma2(h3.x, w2, y2[6]); y2[7] = ffma2(h3.y, w2, y2[7]);
    }
#pragma unroll
    for (int u = 0; u < 8; u++) {
        float a, b;
        unpack2(y0[u], a, b);
        g_x[(n0 + 2 * u) * 384 + t] = a;       g_x[(n0 + 2 * u + 1) * 384 + t] = b;
        unpack2(y1[u], a, b);
        g_x[(n0 + 2 * u) * 384 + 128 + t] = a; g_x[(n0 + 2 * u + 1) * 384 + 128 + t] = b;
        unpack2(y2[u], a, b);
        g_x[(n0 + 2 * u) * 384 + 256 + t] = a; g_x[(n0 + 2 * u + 1) * 384 + 256 + t] = b;
    }
}

// ============================================================================
// K2: edge messages. Thread t owns channels {t,128+t,256+t} (register weights,
// broadcast-attr filter GEMM). Per edge, each warp stages its 4 result rows
// (dq,dmu_xyz x 32 channels) in warp-private smem (double-buffered), then
// re-reads as channel-quads and issues red.global.add.v4 — 4 vec4 REDs/warp
// instead of 128 scalar REDs.
// TE=32 edges per block; grid = E/TE = 10000.
// ============================================================================
#define TE 32
__global__ __launch_bounds__(128) void k_edge(
    const int*   __restrict__ eidx,     // [2,E]
    const float* __restrict__ ew,       // [E]
    const float* __restrict__ evers,    // [E,3]
    const float* __restrict__ eattr,    // [E,B]
    const float* __restrict__ Wf,       // [B,384]
    const float* __restrict__ bf,       // [384]
    const float* __restrict__ mu)       // [N,3,128]
{
    __shared__ u64   sA2[BB * TE];        // pack2(a,a) at [b*TE + e]  (5 KB)
    __shared__ float sFc[TE];
    __shared__ float sV[3 * TE];
    __shared__ int   sIJ[2 * TE];
    __shared__ float sSt[4][2][4][32];    // [warp][buf][row][chan]  (4 KB)

    const int t = threadIdx.x;
    const int w = t >> 5;
    const int l = t & 31;
    const int e0 = blockIdx.x * TE;

    // stage edge data
    for (int idx = t; idx < TE * BB; idx += 128) {
        const int e = idx / BB, b = idx % BB;
        const float a = __ldg(&eattr[(e0 + e) * BB + b]);
        sA2[b * TE + e] = pack2(a, a);
    }
    if (t < TE) {
        const int e = e0 + t;
        sIJ[t]      = eidx[e];
        sIJ[TE + t] = eidx[EE + e];
        const float wgt = __ldg(&ew[e]);
        sFc[t] = (wgt < RCUT) ? 0.5f * (cosf((PI_F / RCUT) * wgt) + 1.0f) : 0.0f;
        sV[t]          = __ldg(&evers[e * 3 + 0]);
        sV[TE + t]     = __ldg(&evers[e * 3 + 1]);
        sV[2 * TE + t] = __ldg(&evers[e * 3 + 2]);
    }

    // register-resident filter weights for my 3 channels
    u64 wAB[BB], wCC[BB];
#pragma unroll
    for (int b = 0; b < BB; b++) {
        const float wa = __ldg(&Wf[b * 384 + t]);
        const float wb = __ldg(&Wf[b * 384 + 128 + t]);
        const float wc = __ldg(&Wf[b * 384 + 256 + t]);
        wAB[b] = pack2(wa, wb);
        wCC[b] = pack2(wc, wc);
    }
    const u64 bAB = pack2(__ldg(&bf[t]), __ldg(&bf[128 + t]));
    const u64 bCC = pack2(__ldg(&bf[256 + t]), 0.0f);
    __syncthreads();

    // RED-phase constants for this lane
    const int rr = l >> 3;               // 0..3: dq, dmu_x, dmu_y, dmu_z
    const int cq = w * 32 + (l & 7) * 4; // channel-quad base

    for (int e = 0; e < TE; e++) {
        const int i = sIJ[e];
        const int j = sIJ[TE + e];
        const float fc = sFc[e];
        const float vx = sV[e], vy = sV[TE + e], vz = sV[2 * TE + e];

        u64 acc = bAB, accC = bCC;
#pragma unroll
        for (int b = 0; b < BB; b++) {
            const u64 a2 = sA2[b * TE + e];   // broadcast LDS.64
            acc  = ffma2(wAB[b], a2, acc);
            accC = ffma2(wCC[b], a2, accC);
        }
        float wijA, wijB, wijC, dead;
        unpack2(acc, wijA, wijB);
        unpack2(accC, wijC, dead);
        wijA *= fc; wijB *= fc; wijC *= fc;

        const float xA = __ldg(&g_x[j * 384 + t]);
        const float xB = __ldg(&g_x[j * 384 + 128 + t]);
        const float xC = __ldg(&g_x[j * 384 + 256 + t]);
        const float m0 = __ldg(&mu[j * 384 + t]);
        const float m1 = __ldg(&mu[j * 384 + 128 + t]);
        const float m2 = __ldg(&mu[j * 384 + 256 + t]);

        const float dq = xA * wijA;
        const float dR = xB * wijB;
        const float dM = xC * wijC;

        const int buf = e & 1;
        sSt[w][buf][0][l] = dq;
        sSt[w][buf][1][l] = dR * vx + dM * m0;
        sSt[w][buf][2][l] = dR * vy + dM * m1;
        sSt[w][buf][3][l] = dR * vz + dM * m2;
        __syncwarp();

        const float4 v = *(const float4*)&sSt[w][buf][rr][(l & 7) * 4];
        float* base = (rr == 0) ? &g_dq[i * 128 + cq]
                                : &g_dmu[i * 384 + (rr - 1) * 128 + cq];
        red_add_v4(base, v);
    }
}

// ============================================================================
// K3: PaiNN mixing. block = 128 threads, 8 nodes per block, grid = 2500.
// ============================================================================
__global__ __launch_bounds__(128) void k_mix(
    const float* __restrict__ q,
    const float* __restrict__ mu,
    const float* __restrict__ Wmix,   // [128,256]
    const float* __restrict__ Wm1,    // [256,128]
    const float* __restrict__ bm1,    // [128]
    const float* __restrict__ Wm2,    // [128,384]
    const float* __restrict__ bm2,    // [384]
    float* __restrict__ out_q,        // [N,128]
    float* __restrict__ out_mu)       // [N,3,128]
{
    __shared__ float sMuT[128 * 24];   // [k][v*8+n]  (mun transposed)
    __shared__ float sAW[128 * 24];    // stash of mu_W per (t-channel)[v*8+n]
    __shared__ float sCtx[256 * 8];    // [k][n]
    __shared__ float sH2[128 * 8];     // [k][n]
    const int t = threadIdx.x;
    const int n0 = blockIdx.x * 8;

    float qn[8];
#pragma unroll
    for (int v = 0; v < 3; v++)
#pragma unroll
        for (int n = 0; n < 8; n++) {
            const int gi = (n0 + n) * 384 + v * 128 + t;
            sMuT[t * 24 + v * 8 + n] = mu[gi] + g_dmu[gi];
        }
#pragma unroll
    for (int n = 0; n < 8; n++)
        qn[n] = q[(n0 + n) * 128 + t] + g_dq[(n0 + n) * 128 + t];
    __syncthreads();

    // fused: mu_V and mu_W GEMMs over one sMuT pass
    u64 aV[12], aW[12];
#pragma unroll
    for (int u = 0; u < 12; u++) { aV[u] = 0ull; aW[u] = 0ull; }
#pragma unroll 2
    for (int k = 0; k < 128; k++) {
        const float wv = __ldg(&Wmix[k * 256 + t]);
        const float ww = __ldg(&Wmix[k * 256 + 128 + t]);
        const u64 wv2 = pack2(wv, wv);
        const u64 ww2 = pack2(ww, ww);
        const ulonglong2* r = (const ulonglong2*)&sMuT[k * 24];
#pragma unroll
        for (int u = 0; u < 6; u++) {
            const ulonglong2 m = r[u];
            aV[2 * u]     = ffma2(m.x, wv2, aV[2 * u]);
            aV[2 * u + 1] = ffma2(m.y, wv2, aV[2 * u + 1]);
            aW[2 * u]     = ffma2(m.x, ww2, aW[2 * u]);
            aW[2 * u + 1] = ffma2(m.y, ww2, aW[2 * u + 1]);
        }
    }
    float av[24], aw[24];
#pragma unroll
    for (int u = 0; u < 12; u++) {
        unpack2(aV[u], av[2 * u], av[2 * u + 1]);
        unpack2(aW[u], aw[2 * u], aw[2 * u + 1]);
    }

    float Vn[8], sdot[8];
#pragma unroll
    for (int n = 0; n < 8; n++) {
        Vn[n] = sqrtf(av[n] * av[n] + av[8 + n] * av[8 + n]
                      + av[16 + n] * av[16 + n] + EPSN);
        sdot[n] = av[n] * aw[n] + av[8 + n] * aw[8 + n] + av[16 + n] * aw[16 + n];
    }
#pragma unroll
    for (int u = 0; u < 24; u++) sAW[t * 24 + u] = aw[u];

#pragma unroll
    for (int n = 0; n < 8; n++) {
        sCtx[t * 8 + n] = qn[n];
        sCtx[(128 + t) * 8 + n] = Vn[n];
    }
    __syncthreads();

    u64 h[4];
    {
        const float bb = __ldg(&bm1[t]);
        const u64 bb2 = pack2(bb, bb);
#pragma unroll
        for (int u = 0; u < 4; u++) h[u] = bb2;
    }
#pragma unroll 4
    for (int k = 0; k < 256; k++) {
        const float w = __ldg(&Wm1[k * 128 + t]);
        const u64 w2 = pack2(w, w);
        const ulonglong2* r = (const ulonglong2*)&sCtx[k * 8];
        const ulonglong2 ca = r[0], cb = r[1];
        h[0] = ffma2(ca.x, w2, h[0]); h[1] = ffma2(ca.y, w2, h[1]);
        h[2] = ffma2(cb.x, w2, h[2]); h[3] = ffma2(cb.y, w2, h[3]);
    }
#pragma unroll
    for (int u = 0; u < 4; u++) {
        float lo, hi; unpack2(h[u], lo, hi);
        sH2[t * 8 + 2 * u]     = silu_f(lo);
        sH2[t * 8 + 2 * u + 1] = silu_f(hi);
    }
    __syncthreads();

    u64 ya[4], yb[4], yc[4];
    {
        const float c0 = __ldg(&bm2[t]);
        const float c1 = __ldg(&bm2[128 + t]);
        const float c2 = __ldg(&bm2[256 + t]);
        const u64 pa = pack2(c0, c0), pb = pack2(c1, c1), pc = pack2(c2, c2);
#pragma unroll
        for (int u = 0; u < 4; u++) { ya[u] = pa; yb[u] = pb; yc[u] = pc; }
    }
#pragma unroll 2
    for (int k = 0; k < 128; k++) {
        const float f0 = __ldg(&Wm2[k * 384 + t]);
        const float f1 = __ldg(&Wm2[k * 384 + 128 + t]);
        const float f2 = __ldg(&Wm2[k * 384 + 256 + t]);
        const u64 w0 = pack2(f0, f0), w1 = pack2(f1, f1), w2 = pack2(f2, f2);
        const ulonglong2* r = (const ulonglong2*)&sH2[k * 8];
        const ulonglong2 ha = r[0], hb = r[1];
        ya[0] = ffma2(ha.x, w0, ya[0]); ya[1] = ffma2(ha.y, w0, ya[1]);
        ya[2] = ffma2(hb.x, w0, ya[2]); ya[3] = ffma2(hb.y, w0, ya[3]);
        yb[0] = ffma2(ha.x, w1, yb[0]); yb[1] = ffma2(ha.y, w1, yb[1]);
        yb[2] = ffma2(hb.x, w1, yb[2]); yb[3] = ffma2(hb.y, w1, yb[3]);
        yc[0] = ffma2(ha.x, w2, yc[0]); yc[1] = ffma2(ha.y, w2, yc[1]);
        yc[2] = ffma2(hb.x, w2, yc[2]); yc[3] = ffma2(hb.y, w2, yc[3]);
    }
    float Ya[8], Yb[8], Yc[8];
#pragma unroll
    for (int u = 0; u < 4; u++) {
        unpack2(ya[u], Ya[2 * u], Ya[2 * u + 1]);
        unpack2(yb[u], Yb[2 * u], Yb[2 * u + 1]);
        unpack2(yc[u], Yc[2 * u], Yc[2 * u + 1]);
    }

#pragma unroll
    for (int n = 0; n < 8; n++) {
        out_q[(n0 + n) * 128 + t] = qn[n] + Ya[n] + Yc[n] * sdot[n];
#pragma unroll
        for (int v = 0; v < 3; v++)
            out_mu[(n0 + n) * 384 + v * 128 + t] =
                sMuT[t * 24 + v * 8 + n] + Yb[n] * sAW[t * 24 + v * 8 + n];
    }
}

// ============================================================================
extern "C" void kernel_launch(void* const* d_in, const int* in_sizes, int n_in,
                              void* d_out, int out_size)
{
    const float* q     = (const float*)d_in[0];
    const float* mu    = (const float*)d_in[1];
    const int*   eidx  = (const int*)d_in[2];
    const float* ew    = (const float*)d_in[3];
    const float* evers = (const float*)d_in[4];
    const float* eattr = (const float*)d_in[5];
    const float* Wf    = (const float*)d_in[6];
    const float* bf    = (const float*)d_in[7];
    const float* W1    = (const float*)d_in[8];
    const float* b1    = (const float*)d_in[9];
    const float* W2    = (const float*)d_in[10];
    const float* b2    = (const float*)d_in[11];
    const float* Wmix  = (const float*)d_in[12];
    const float* Wm1   = (const float*)d_in[13];
    const float* bm1   = (const float*)d_in[14];
    const float* Wm2   = (const float*)d_in[15];
    const float* bm2   = (const float*)d_in[16];

    float* out   = (float*)d_out;
    float* out_q = out;
    float* out_mu = out + (size_t)NN * 128;

    k_node_mlp<<<NN / 16, 128>>>(q, W1, b1, W2, b2);
    k_edge<<<EE / TE, 128>>>(eidx, ew, evers, eattr, Wf, bf, mu);
    k_mix<<<NN / 8, 128>>>(q, mu, Wmix, Wm1, bm1, Wm2, bm2, out_q, out_mu);
}